// round 1
// baseline (speedup 1.0000x reference)
#include <cuda_runtime.h>
#include <math.h>

#define EMBED  1024
#define NHEADS 16
#define HDIM   64
#define BATCH  2
#define TQ     2048
#define TK     2048
#define MROWS  (BATCH*TQ)   // 4096

// Scratch (allocation-free rule: __device__ globals)
__device__ float g_Q [(size_t)MROWS * EMBED];        // 16 MB
__device__ float g_KV[(size_t)MROWS * 2 * EMBED];    // 32 MB
__device__ float g_O [(size_t)MROWS * EMBED];        // 16 MB

// ---------------------------------------------------------------------------
// Tiled fp32 GEMM + bias: C[M,N] = A[M,K] @ W[K,N] + bias[N]
// 64x64 block tile, BK=16, 256 threads, 4x4 per thread.
// ---------------------------------------------------------------------------
__global__ __launch_bounds__(256) void gemm_bias_kernel(
    const float* __restrict__ A, const float* __restrict__ W,
    const float* __restrict__ bias, float* __restrict__ C,
    int M, int N, int K)
{
    __shared__ float As[64 * 16];
    __shared__ float Bs[16 * 64];

    const int tid = threadIdx.x;
    const int tx  = tid & 15;
    const int ty  = tid >> 4;
    const int row0 = blockIdx.y * 64;
    const int col0 = blockIdx.x * 64;

    float acc[4][4] = {};

    for (int k0 = 0; k0 < K; k0 += 16) {
        #pragma unroll
        for (int i = 0; i < 4; i++) {
            int e = tid + i * 256;
            int ra = e >> 4, ca = e & 15;
            As[e] = A[(size_t)(row0 + ra) * K + k0 + ca];
            int rb = e >> 6, cb = e & 63;
            Bs[e] = W[(size_t)(k0 + rb) * N + col0 + cb];
        }
        __syncthreads();

        #pragma unroll
        for (int kk = 0; kk < 16; kk++) {
            float a[4], b[4];
            #pragma unroll
            for (int i = 0; i < 4; i++) a[i] = As[(ty * 4 + i) * 16 + kk];
            #pragma unroll
            for (int j = 0; j < 4; j++) b[j] = Bs[kk * 64 + tx * 4 + j];
            #pragma unroll
            for (int i = 0; i < 4; i++)
                #pragma unroll
                for (int j = 0; j < 4; j++)
                    acc[i][j] = fmaf(a[i], b[j], acc[i][j]);
        }
        __syncthreads();
    }

    #pragma unroll
    for (int j = 0; j < 4; j++) {
        float bj = bias[col0 + tx * 4 + j];
        #pragma unroll
        for (int i = 0; i < 4; i++)
            C[(size_t)(row0 + ty * 4 + i) * N + col0 + tx * 4 + j] = acc[i][j] + bj;
    }
}

// ---------------------------------------------------------------------------
// Flash-attention core: per (b,h, q-tile of 64), loop k-tiles of 64.
// Online softmax in registers; P staged through smem for the PV GEMM.
// XOR swizzle keeps all three 64x64 buffers at exactly 48 KB static smem.
// ---------------------------------------------------------------------------
__device__ __forceinline__ int swz(int r, int c) { return r * 64 + (c ^ (r & 31)); }

__global__ __launch_bounds__(256) void attn_kernel(
    const float* __restrict__ Q, const float* __restrict__ KV, float* __restrict__ O)
{
    __shared__ float Qs [64 * 64];
    __shared__ float KVs[64 * 64];   // holds K tile, then reused for V tile
    __shared__ float Ps [64 * 64];

    const int tid = threadIdx.x;
    const int tx  = tid & 15;
    const int ty  = tid >> 4;
    const int bh  = blockIdx.y;
    const int b   = bh >> 4;
    const int h   = bh & 15;
    const int q0  = blockIdx.x * 64;
    const float scale = 0.125f;   // 1/sqrt(64), folded into Q

    for (int e = tid; e < 4096; e += 256) {
        int r = e >> 6, d = e & 63;
        Qs[swz(r, d)] = Q[(size_t)(b * TQ + q0 + r) * EMBED + h * HDIM + d] * scale;
    }

    float m[4], l[4], o[4][4];
    #pragma unroll
    for (int i = 0; i < 4; i++) {
        m[i] = -1e30f; l[i] = 0.0f;
        #pragma unroll
        for (int j = 0; j < 4; j++) o[i][j] = 0.0f;
    }

    for (int kt = 0; kt < TK; kt += 64) {
        __syncthreads();   // prev PV reads done (and Qs visible on first iter)

        // ---- load K tile [k][d] ----
        for (int e = tid; e < 4096; e += 256) {
            int r = e >> 6, d = e & 63;
            KVs[swz(r, d)] = KV[(size_t)(b * TK + kt + r) * (2 * EMBED) + h * HDIM + d];
        }
        __syncthreads();

        // ---- S = Q @ K^T (scaled) ----
        float s[4][4] = {};
        #pragma unroll 8
        for (int kk = 0; kk < 64; kk++) {
            float a[4], bb[4];
            #pragma unroll
            for (int i = 0; i < 4; i++) a[i]  = Qs [swz(ty * 4 + i, kk)];
            #pragma unroll
            for (int j = 0; j < 4; j++) bb[j] = KVs[swz(tx * 4 + j, kk)];
            #pragma unroll
            for (int i = 0; i < 4; i++)
                #pragma unroll
                for (int j = 0; j < 4; j++)
                    s[i][j] = fmaf(a[i], bb[j], s[i][j]);
        }

        // ---- online softmax (row reductions across the 16 tx lanes) ----
        #pragma unroll
        for (int i = 0; i < 4; i++) {
            float tmax = fmaxf(fmaxf(s[i][0], s[i][1]), fmaxf(s[i][2], s[i][3]));
            #pragma unroll
            for (int off = 8; off >= 1; off >>= 1)
                tmax = fmaxf(tmax, __shfl_xor_sync(0xffffffffu, tmax, off, 16));
            float mn    = fmaxf(m[i], tmax);
            float alpha = __expf(m[i] - mn);
            float rsum  = 0.0f;
            #pragma unroll
            for (int j = 0; j < 4; j++) {
                s[i][j] = __expf(s[i][j] - mn);
                rsum += s[i][j];
            }
            #pragma unroll
            for (int off = 8; off >= 1; off >>= 1)
                rsum += __shfl_xor_sync(0xffffffffu, rsum, off, 16);
            l[i] = l[i] * alpha + rsum;
            m[i] = mn;
            #pragma unroll
            for (int j = 0; j < 4; j++) o[i][j] *= alpha;
        }

        __syncthreads();   // all threads done reading K tile

        // ---- stage P, load V tile over K tile ----
        #pragma unroll
        for (int i = 0; i < 4; i++)
            #pragma unroll
            for (int j = 0; j < 4; j++)
                Ps[swz(ty * 4 + i, tx * 4 + j)] = s[i][j];

        for (int e = tid; e < 4096; e += 256) {
            int r = e >> 6, d = e & 63;
            KVs[swz(r, d)] =
                KV[(size_t)(b * TK + kt + r) * (2 * EMBED) + EMBED + h * HDIM + d];
        }
        __syncthreads();

        // ---- O += P @ V ----
        #pragma unroll 8
        for (int kk = 0; kk < 64; kk++) {
            float a[4], bb[4];
            #pragma unroll
            for (int i = 0; i < 4; i++) a[i]  = Ps [swz(ty * 4 + i, kk)];
            #pragma unroll
            for (int j = 0; j < 4; j++) bb[j] = KVs[swz(kk, tx * 4 + j)];
            #pragma unroll
            for (int i = 0; i < 4; i++)
                #pragma unroll
                for (int j = 0; j < 4; j++)
                    o[i][j] = fmaf(a[i], bb[j], o[i][j]);
        }
    }

    #pragma unroll
    for (int i = 0; i < 4; i++) {
        float inv = 1.0f / l[i];
        #pragma unroll
        for (int j = 0; j < 4; j++)
            O[(size_t)(b * TQ + q0 + ty * 4 + i) * EMBED + h * HDIM + tx * 4 + j]
                = o[i][j] * inv;
    }
}

// ---------------------------------------------------------------------------
// kernel_launch: Qproj -> KVproj -> attention -> Oproj (4 launches, capturable)
// ---------------------------------------------------------------------------
extern "C" void kernel_launch(void* const* d_in, const int* in_sizes, int n_in,
                              void* d_out, int out_size)
{
    const float* query   = (const float*)d_in[0];
    const float* context = (const float*)d_in[1];
    const float* Wq      = (const float*)d_in[2];
    const float* bq      = (const float*)d_in[3];
    const float* Wkv     = (const float*)d_in[4];
    const float* bkv     = (const float*)d_in[5];
    const float* Wo      = (const float*)d_in[6];
    const float* bo      = (const float*)d_in[7];
    float* out = (float*)d_out;

    float *qbuf = nullptr, *kvbuf = nullptr, *obuf = nullptr;
    cudaGetSymbolAddress((void**)&qbuf,  g_Q);
    cudaGetSymbolAddress((void**)&kvbuf, g_KV);
    cudaGetSymbolAddress((void**)&obuf,  g_O);

    dim3 blk(256);

    // Q projection: [4096,1024] = query @ Wq + bq
    gemm_bias_kernel<<<dim3(EMBED / 64, MROWS / 64), blk>>>(
        query, Wq, bq, qbuf, MROWS, EMBED, EMBED);

    // KV projection: [4096,2048] = context @ Wkv + bkv
    gemm_bias_kernel<<<dim3(2 * EMBED / 64, MROWS / 64), blk>>>(
        context, Wkv, bkv, kvbuf, MROWS, 2 * EMBED, EMBED);

    // Attention core: 32 q-tiles x 32 (b,h) pairs
    attn_kernel<<<dim3(TQ / 64, BATCH * NHEADS), blk>>>(qbuf, kvbuf, obuf);

    // Output projection: out = O @ Wo + bo
    gemm_bias_kernel<<<dim3(EMBED / 64, MROWS / 64), blk>>>(
        obuf, Wo, bo, out, MROWS, EMBED, EMBED);
}

// round 2
// speedup vs baseline: 3.7622x; 3.7622x over previous
#include <cuda_runtime.h>
#include <math.h>
#include <stdint.h>

#define EMBED  1024
#define NHEADS 16
#define HDIM   64
#define BATCH  2
#define TQ     2048
#define TK     2048
#define MROWS  (BATCH*TQ)   // 4096

// Scratch (allocation-free rule: __device__ globals)
__device__ float g_Q [(size_t)MROWS * EMBED];        // 16 MB
__device__ float g_KV[(size_t)MROWS * 2 * EMBED];    // 32 MB
__device__ float g_O [(size_t)MROWS * EMBED];        // 16 MB

// ---------------------------------------------------------------------------
// helpers
// ---------------------------------------------------------------------------
__device__ __forceinline__ uint32_t f2tf(float f) {
    uint32_t u;
    asm("cvt.rna.tf32.f32 %0, %1;" : "=r"(u) : "f"(f));
    return u;
}

// D += A@B, m16n8k8 tf32, A row-major, B col-major
__device__ __forceinline__ void mma_tf32(float* d, const uint32_t* a, const uint32_t* b) {
    asm volatile(
        "mma.sync.aligned.m16n8k8.row.col.f32.tf32.tf32.f32 "
        "{%0,%1,%2,%3}, {%4,%5,%6,%7}, {%8,%9}, {%0,%1,%2,%3};"
        : "+f"(d[0]), "+f"(d[1]), "+f"(d[2]), "+f"(d[3])
        : "r"(a[0]), "r"(a[1]), "r"(a[2]), "r"(a[3]), "r"(b[0]), "r"(b[1]));
}

// ---------------------------------------------------------------------------
// Projection GEMM: C[M,N] = A[M,K] @ W[K,N] + bias, tf32 tensor cores.
// Block tile 128x128, BK=32, 256 threads (8 warps, 2x4), warp tile 64x32.
// ---------------------------------------------------------------------------
__global__ __launch_bounds__(256) void gemm_tc_kernel(
    const float* __restrict__ A, const float* __restrict__ W,
    const float* __restrict__ bias, float* __restrict__ C,
    int M, int N, int K)
{
    __shared__ uint32_t As[128 * 36];   // pad 32->36: conflict-free frag loads
    __shared__ uint32_t Ws[32 * 128];   // col swizzle: c ^ ((r&3)<<3)

    const int tid    = threadIdx.x;
    const int lane   = tid & 31;
    const int wid    = tid >> 5;
    const int gid    = lane >> 2;       // 0..7
    const int tid4   = lane & 3;        // 0..3
    const int warp_m = wid & 1;         // 0..1  -> 64 rows
    const int warp_n = wid >> 1;        // 0..3  -> 32 cols
    const int row0   = blockIdx.y * 128;
    const int col0   = blockIdx.x * 128;

    float acc[4][4][4] = {};

    for (int k0 = 0; k0 < K; k0 += 32) {
        // ---- load A tile 128x32 ----
        #pragma unroll
        for (int p = 0; p < 4; p++) {
            int idx = tid + p * 256;            // float4 index, 1024 total
            int r = idx >> 3, c4 = (idx & 7) * 4;
            float4 v = *reinterpret_cast<const float4*>(
                &A[(size_t)(row0 + r) * K + k0 + c4]);
            uint4 t = { f2tf(v.x), f2tf(v.y), f2tf(v.z), f2tf(v.w) };
            *reinterpret_cast<uint4*>(&As[r * 36 + c4]) = t;
        }
        // ---- load W tile 32x128 (swizzled) ----
        #pragma unroll
        for (int p = 0; p < 4; p++) {
            int idx = tid + p * 256;
            int r = idx >> 5, c4 = (idx & 31) * 4;
            float4 v = *reinterpret_cast<const float4*>(
                &W[(size_t)(k0 + r) * N + col0 + c4]);
            uint4 t = { f2tf(v.x), f2tf(v.y), f2tf(v.z), f2tf(v.w) };
            *reinterpret_cast<uint4*>(&Ws[r * 128 + (c4 ^ ((r & 3) << 3))]) = t;
        }
        __syncthreads();

        #pragma unroll
        for (int ks = 0; ks < 4; ks++) {
            const int k = ks * 8;
            uint32_t a[4][4];
            #pragma unroll
            for (int mi = 0; mi < 4; mi++) {
                int rb = warp_m * 64 + mi * 16;
                a[mi][0] = As[(rb + gid)     * 36 + k + tid4];
                a[mi][1] = As[(rb + gid + 8) * 36 + k + tid4];
                a[mi][2] = As[(rb + gid)     * 36 + k + tid4 + 4];
                a[mi][3] = As[(rb + gid + 8) * 36 + k + tid4 + 4];
            }
            uint32_t b[4][2];
            #pragma unroll
            for (int ni = 0; ni < 4; ni++) {
                int cb = warp_n * 32 + ni * 8;
                int r1 = k + tid4, r2 = k + tid4 + 4;
                b[ni][0] = Ws[r1 * 128 + ((cb + gid) ^ ((r1 & 3) << 3))];
                b[ni][1] = Ws[r2 * 128 + ((cb + gid) ^ ((r2 & 3) << 3))];
            }
            #pragma unroll
            for (int mi = 0; mi < 4; mi++)
                #pragma unroll
                for (int ni = 0; ni < 4; ni++)
                    mma_tf32(acc[mi][ni], a[mi], b[ni]);
        }
        __syncthreads();
    }

    // ---- epilogue: + bias ----
    #pragma unroll
    for (int mi = 0; mi < 4; mi++) {
        int row = row0 + warp_m * 64 + mi * 16 + gid;
        #pragma unroll
        for (int ni = 0; ni < 4; ni++) {
            int col = col0 + warp_n * 32 + ni * 8 + 2 * tid4;
            float b0 = bias[col], b1 = bias[col + 1];
            float2 v0 = { acc[mi][ni][0] + b0, acc[mi][ni][1] + b1 };
            float2 v1 = { acc[mi][ni][2] + b0, acc[mi][ni][3] + b1 };
            *reinterpret_cast<float2*>(&C[(size_t)row       * N + col]) = v0;
            *reinterpret_cast<float2*>(&C[(size_t)(row + 8) * N + col]) = v1;
        }
    }
}

// ---------------------------------------------------------------------------
// Flash attention with tf32 mma. Block: 128 threads = 4 warps.
// Tile Bq=64, Bk=64, D=64. Each warp owns 16 q-rows -> warp-local softmax.
// Smem: Qs + Ks/Vs + Ps, each 64x64, XOR-swizzled, 48KB exactly.
// ---------------------------------------------------------------------------
__device__ __forceinline__ int asw(int r, int c) { return r * 64 + (c ^ ((r & 7) << 3)); }

__global__ __launch_bounds__(128) void attn_tc_kernel(
    const float* __restrict__ Q, const float* __restrict__ KV, float* __restrict__ O)
{
    __shared__ uint32_t Qs[64 * 64];
    __shared__ uint32_t Ks[64 * 64];   // K tile, reused for V tile
    __shared__ uint32_t Ps[64 * 64];

    const int tid  = threadIdx.x;
    const int lane = tid & 31;
    const int wid  = tid >> 5;          // 0..3
    const int gid  = lane >> 2;
    const int tid4 = lane & 3;
    const int rb   = wid * 16;          // warp's q-row base within tile
    const int bh   = blockIdx.y;
    const int b    = bh >> 4;
    const int h    = bh & 15;
    const int q0   = blockIdx.x * 64;

    // ---- load Q tile (scale folded in) ----
    for (int idx = tid; idx < 1024; idx += 128) {       // 64 rows x 16 float4
        int r = idx >> 4, c4 = (idx & 15) * 4;
        float4 v = *reinterpret_cast<const float4*>(
            &Q[(size_t)(b * TQ + q0 + r) * EMBED + h * HDIM + c4]);
        uint4 t = { f2tf(v.x * 0.125f), f2tf(v.y * 0.125f),
                    f2tf(v.z * 0.125f), f2tf(v.w * 0.125f) };
        *reinterpret_cast<uint4*>(&Qs[asw(r, c4)]) = t;
    }

    float m0 = -1e30f, m1 = -1e30f, l0 = 0.0f, l1 = 0.0f;
    float o[8][4] = {};

    for (int kt = 0; kt < TK; kt += 64) {
        __syncthreads();    // prev PV reads done; Qs visible on first iter

        // ---- K tile ----
        for (int idx = tid; idx < 1024; idx += 128) {
            int r = idx >> 4, c4 = (idx & 15) * 4;
            float4 v = *reinterpret_cast<const float4*>(
                &KV[(size_t)(b * TK + kt + r) * (2 * EMBED) + h * HDIM + c4]);
            uint4 t = { f2tf(v.x), f2tf(v.y), f2tf(v.z), f2tf(v.w) };
            *reinterpret_cast<uint4*>(&Ks[asw(r, c4)]) = t;
        }
        __syncthreads();

        // ---- S = Q @ K^T ----
        float s[8][4] = {};
        #pragma unroll
        for (int ks = 0; ks < 8; ks++) {
            const int k = ks * 8;
            uint32_t a[4];
            a[0] = Qs[asw(rb + gid,     k + tid4)];
            a[1] = Qs[asw(rb + gid + 8, k + tid4)];
            a[2] = Qs[asw(rb + gid,     k + tid4 + 4)];
            a[3] = Qs[asw(rb + gid + 8, k + tid4 + 4)];
            #pragma unroll
            for (int ni = 0; ni < 8; ni++) {
                const int n = ni * 8;
                uint32_t bfr[2];
                bfr[0] = Ks[asw(n + gid, k + tid4)];
                bfr[1] = Ks[asw(n + gid, k + tid4 + 4)];
                mma_tf32(s[ni], a, bfr);
            }
        }

        // ---- online softmax (rows gid and gid+8, quad-lane reductions) ----
        float tmax0 = -1e30f, tmax1 = -1e30f;
        #pragma unroll
        for (int ni = 0; ni < 8; ni++) {
            tmax0 = fmaxf(tmax0, fmaxf(s[ni][0], s[ni][1]));
            tmax1 = fmaxf(tmax1, fmaxf(s[ni][2], s[ni][3]));
        }
        tmax0 = fmaxf(tmax0, __shfl_xor_sync(0xffffffffu, tmax0, 1, 4));
        tmax0 = fmaxf(tmax0, __shfl_xor_sync(0xffffffffu, tmax0, 2, 4));
        tmax1 = fmaxf(tmax1, __shfl_xor_sync(0xffffffffu, tmax1, 1, 4));
        tmax1 = fmaxf(tmax1, __shfl_xor_sync(0xffffffffu, tmax1, 2, 4));

        float mn0 = fmaxf(m0, tmax0), mn1 = fmaxf(m1, tmax1);
        float al0 = __expf(m0 - mn0), al1 = __expf(m1 - mn1);
        float rs0 = 0.0f, rs1 = 0.0f;
        #pragma unroll
        for (int ni = 0; ni < 8; ni++) {
            s[ni][0] = __expf(s[ni][0] - mn0);
            s[ni][1] = __expf(s[ni][1] - mn0);
            s[ni][2] = __expf(s[ni][2] - mn1);
            s[ni][3] = __expf(s[ni][3] - mn1);
            rs0 += s[ni][0] + s[ni][1];
            rs1 += s[ni][2] + s[ni][3];
        }
        rs0 += __shfl_xor_sync(0xffffffffu, rs0, 1, 4);
        rs0 += __shfl_xor_sync(0xffffffffu, rs0, 2, 4);
        rs1 += __shfl_xor_sync(0xffffffffu, rs1, 1, 4);
        rs1 += __shfl_xor_sync(0xffffffffu, rs1, 2, 4);
        l0 = l0 * al0 + rs0;  m0 = mn0;
        l1 = l1 * al1 + rs1;  m1 = mn1;
        #pragma unroll
        for (int ni = 0; ni < 8; ni++) {
            o[ni][0] *= al0; o[ni][1] *= al0;
            o[ni][2] *= al1; o[ni][3] *= al1;
        }

        // ---- stage P (warp-local rows) ----
        #pragma unroll
        for (int ni = 0; ni < 8; ni++) {
            int col = ni * 8 + 2 * tid4;
            Ps[asw(rb + gid, col)]         = f2tf(s[ni][0]);
            Ps[asw(rb + gid, col) + 1]     = f2tf(s[ni][1]);
            Ps[asw(rb + gid + 8, col)]     = f2tf(s[ni][2]);
            Ps[asw(rb + gid + 8, col) + 1] = f2tf(s[ni][3]);
        }

        __syncthreads();   // all warps done reading Ks before V overwrite

        // ---- V tile ----
        for (int idx = tid; idx < 1024; idx += 128) {
            int r = idx >> 4, c4 = (idx & 15) * 4;
            float4 v = *reinterpret_cast<const float4*>(
                &KV[(size_t)(b * TK + kt + r) * (2 * EMBED) + EMBED + h * HDIM + c4]);
            uint4 t = { f2tf(v.x), f2tf(v.y), f2tf(v.z), f2tf(v.w) };
            *reinterpret_cast<uint4*>(&Ks[asw(r, c4)]) = t;
        }
        __syncthreads();

        // ---- O += P @ V ----
        #pragma unroll
        for (int ks = 0; ks < 8; ks++) {
            const int k = ks * 8;
            uint32_t a[4];
            a[0] = Ps[asw(rb + gid,     k + tid4)];
            a[1] = Ps[asw(rb + gid + 8, k + tid4)];
            a[2] = Ps[asw(rb + gid,     k + tid4 + 4)];
            a[3] = Ps[asw(rb + gid + 8, k + tid4 + 4)];
            #pragma unroll
            for (int ni = 0; ni < 8; ni++) {
                const int n = ni * 8;
                uint32_t bfr[2];
                bfr[0] = Ks[asw(k + tid4,     n + gid)];
                bfr[1] = Ks[asw(k + tid4 + 4, n + gid)];
                mma_tf32(o[ni], a, bfr);
            }
        }
    }

    // ---- write O (normalize) ----
    float inv0 = 1.0f / l0, inv1 = 1.0f / l1;
    #pragma unroll
    for (int ni = 0; ni < 8; ni++) {
        int col = h * HDIM + ni * 8 + 2 * tid4;
        size_t r0 = (size_t)(b * TQ + q0 + rb + gid) * EMBED;
        size_t r1 = (size_t)(b * TQ + q0 + rb + gid + 8) * EMBED;
        float2 v0 = { o[ni][0] * inv0, o[ni][1] * inv0 };
        float2 v1 = { o[ni][2] * inv1, o[ni][3] * inv1 };
        *reinterpret_cast<float2*>(&O[r0 + col]) = v0;
        *reinterpret_cast<float2*>(&O[r1 + col]) = v1;
    }
}

// ---------------------------------------------------------------------------
// kernel_launch: Qproj -> KVproj -> attention -> Oproj
// ---------------------------------------------------------------------------
extern "C" void kernel_launch(void* const* d_in, const int* in_sizes, int n_in,
                              void* d_out, int out_size)
{
    const float* query   = (const float*)d_in[0];
    const float* context = (const float*)d_in[1];
    const float* Wq      = (const float*)d_in[2];
    const float* bq      = (const float*)d_in[3];
    const float* Wkv     = (const float*)d_in[4];
    const float* bkv     = (const float*)d_in[5];
    const float* Wo      = (const float*)d_in[6];
    const float* bo      = (const float*)d_in[7];
    float* out = (float*)d_out;

    float *qbuf = nullptr, *kvbuf = nullptr, *obuf = nullptr;
    cudaGetSymbolAddress((void**)&qbuf,  g_Q);
    cudaGetSymbolAddress((void**)&kvbuf, g_KV);
    cudaGetSymbolAddress((void**)&obuf,  g_O);

    // Q projection: [4096,1024]
    gemm_tc_kernel<<<dim3(EMBED / 128, MROWS / 128), 256>>>(
        query, Wq, bq, qbuf, MROWS, EMBED, EMBED);

    // KV projection: [4096,2048]
    gemm_tc_kernel<<<dim3(2 * EMBED / 128, MROWS / 128), 256>>>(
        context, Wkv, bkv, kvbuf, MROWS, 2 * EMBED, EMBED);

    // Attention core
    attn_tc_kernel<<<dim3(TQ / 64, BATCH * NHEADS), 128>>>(qbuf, kvbuf, obuf);

    // Output projection
    gemm_tc_kernel<<<dim3(EMBED / 128, MROWS / 128), 256>>>(
        obuf, Wo, bo, out, MROWS, EMBED, EMBED);
}

// round 3
// speedup vs baseline: 4.5933x; 1.2209x over previous
#include <cuda_runtime.h>
#include <math.h>
#include <stdint.h>

#define EMBED  1024
#define NHEADS 16
#define HDIM   64
#define BATCH  2
#define TQ     2048
#define TK     2048
#define MROWS  (BATCH*TQ)   // 4096

__device__ float g_Q [(size_t)MROWS * EMBED];
__device__ float g_KV[(size_t)MROWS * 2 * EMBED];
__device__ float g_O [(size_t)MROWS * EMBED];

// ---------------------------------------------------------------------------
__device__ __forceinline__ uint32_t f2tf(float f) {
    uint32_t u;
    asm("cvt.rna.tf32.f32 %0, %1;" : "=r"(u) : "f"(f));
    return u;
}

__device__ __forceinline__ void mma_tf32(float* d, const uint32_t* a, const uint32_t* b) {
    asm volatile(
        "mma.sync.aligned.m16n8k8.row.col.f32.tf32.tf32.f32 "
        "{%0,%1,%2,%3}, {%4,%5,%6,%7}, {%8,%9}, {%0,%1,%2,%3};"
        : "+f"(d[0]), "+f"(d[1]), "+f"(d[2]), "+f"(d[3])
        : "r"(a[0]), "r"(a[1]), "r"(a[2]), "r"(a[3]), "r"(b[0]), "r"(b[1]));
}

// ---------------------------------------------------------------------------
// Projection GEMM body: 128x128 tile, BK=32, 256 thr, register-prefetch
// double buffering (next K-chunk global loads overlap the MMA burst).
// ---------------------------------------------------------------------------
__device__ __forceinline__ void gemm_tc_body(
    uint32_t* As, uint32_t* Ws,
    const float* __restrict__ A, const float* __restrict__ W,
    const float* __restrict__ bias, float* __restrict__ C,
    int N, int K, int row0, int col0)
{
    const int tid    = threadIdx.x;
    const int lane   = tid & 31;
    const int wid    = tid >> 5;
    const int gid    = lane >> 2;
    const int tid4   = lane & 3;
    const int warp_m = wid & 1;
    const int warp_n = wid >> 1;

    float4 aReg[4], wReg[4];
    #pragma unroll
    for (int p = 0; p < 4; p++) {
        int idx = tid + p * 256;
        int r = idx >> 3, c4 = (idx & 7) * 4;
        aReg[p] = *reinterpret_cast<const float4*>(&A[(size_t)(row0 + r) * K + c4]);
        int rw = idx >> 5, cw = (idx & 31) * 4;
        wReg[p] = *reinterpret_cast<const float4*>(&W[(size_t)rw * N + col0 + cw]);
    }

    float acc[4][4][4] = {};

    for (int k0 = 0; k0 < K; k0 += 32) {
        // ---- commit prefetched regs to smem (tf32 convert) ----
        #pragma unroll
        for (int p = 0; p < 4; p++) {
            int idx = tid + p * 256;
            int r = idx >> 3, c4 = (idx & 7) * 4;
            uint4 t = { f2tf(aReg[p].x), f2tf(aReg[p].y), f2tf(aReg[p].z), f2tf(aReg[p].w) };
            *reinterpret_cast<uint4*>(&As[r * 36 + c4]) = t;
            int rw = idx >> 5, cw = (idx & 31) * 4;
            uint4 tw = { f2tf(wReg[p].x), f2tf(wReg[p].y), f2tf(wReg[p].z), f2tf(wReg[p].w) };
            *reinterpret_cast<uint4*>(&Ws[rw * 128 + (cw ^ ((rw & 3) << 3))]) = tw;
        }
        __syncthreads();

        // ---- issue next chunk's global loads (overlap with MMAs) ----
        if (k0 + 32 < K) {
            #pragma unroll
            for (int p = 0; p < 4; p++) {
                int idx = tid + p * 256;
                int r = idx >> 3, c4 = (idx & 7) * 4;
                aReg[p] = *reinterpret_cast<const float4*>(
                    &A[(size_t)(row0 + r) * K + k0 + 32 + c4]);
                int rw = idx >> 5, cw = (idx & 31) * 4;
                wReg[p] = *reinterpret_cast<const float4*>(
                    &W[(size_t)(k0 + 32 + rw) * N + col0 + cw]);
            }
        }

        #pragma unroll
        for (int ks = 0; ks < 4; ks++) {
            const int k = ks * 8;
            uint32_t a[4][4];
            #pragma unroll
            for (int mi = 0; mi < 4; mi++) {
                int rb = warp_m * 64 + mi * 16;
                a[mi][0] = As[(rb + gid)     * 36 + k + tid4];
                a[mi][1] = As[(rb + gid + 8) * 36 + k + tid4];
                a[mi][2] = As[(rb + gid)     * 36 + k + tid4 + 4];
                a[mi][3] = As[(rb + gid + 8) * 36 + k + tid4 + 4];
            }
            uint32_t b[4][2];
            #pragma unroll
            for (int ni = 0; ni < 4; ni++) {
                int cb = warp_n * 32 + ni * 8;
                int r1 = k + tid4, r2 = k + tid4 + 4;
                b[ni][0] = Ws[r1 * 128 + ((cb + gid) ^ ((r1 & 3) << 3))];
                b[ni][1] = Ws[r2 * 128 + ((cb + gid) ^ ((r2 & 3) << 3))];
            }
            #pragma unroll
            for (int mi = 0; mi < 4; mi++)
                #pragma unroll
                for (int ni = 0; ni < 4; ni++)
                    mma_tf32(acc[mi][ni], a[mi], b[ni]);
        }
        __syncthreads();
    }

    #pragma unroll
    for (int mi = 0; mi < 4; mi++) {
        int row = row0 + warp_m * 64 + mi * 16 + gid;
        #pragma unroll
        for (int ni = 0; ni < 4; ni++) {
            int col = col0 + warp_n * 32 + ni * 8 + 2 * tid4;
            float b0 = bias[col], b1 = bias[col + 1];
            float2 v0 = { acc[mi][ni][0] + b0, acc[mi][ni][1] + b1 };
            float2 v1 = { acc[mi][ni][2] + b0, acc[mi][ni][3] + b1 };
            *reinterpret_cast<float2*>(&C[(size_t)row       * N + col]) = v0;
            *reinterpret_cast<float2*>(&C[(size_t)(row + 8) * N + col]) = v1;
        }
    }
}

// Fused Q + KV projection: grid.x 0..7 -> Q proj (N=1024), 8..23 -> KV (N=2048)
__global__ __launch_bounds__(256) void qkv_proj_kernel(
    const float* __restrict__ query, const float* __restrict__ context,
    const float* __restrict__ Wq, const float* __restrict__ bq,
    const float* __restrict__ Wkv, const float* __restrict__ bkv,
    float* __restrict__ qbuf, float* __restrict__ kvbuf)
{
    __shared__ uint32_t As[128 * 36];
    __shared__ uint32_t Ws[32 * 128];
    const int row0 = blockIdx.y * 128;
    if (blockIdx.x < 8) {
        gemm_tc_body(As, Ws, query, Wq, bq, qbuf, EMBED, EMBED,
                     row0, blockIdx.x * 128);
    } else {
        gemm_tc_body(As, Ws, context, Wkv, bkv, kvbuf, 2 * EMBED, EMBED,
                     row0, (blockIdx.x - 8) * 128);
    }
}

__global__ __launch_bounds__(256) void oproj_kernel(
    const float* __restrict__ A, const float* __restrict__ W,
    const float* __restrict__ bias, float* __restrict__ C)
{
    __shared__ uint32_t As[128 * 36];
    __shared__ uint32_t Ws[32 * 128];
    gemm_tc_body(As, Ws, A, W, bias, C, EMBED, EMBED,
                 blockIdx.y * 128, blockIdx.x * 128);
}

// ---------------------------------------------------------------------------
// Flash attention, tf32 mma. 128 thr = 4 warps, warp-local softmax.
// Dynamic smem 64KB: Qs | Ks | Vs | Ps (separate V buffer -> 2 syncs/tile),
// register prefetch overlaps all global loads with MMA/softmax.
// ---------------------------------------------------------------------------
__device__ __forceinline__ int asw(int r, int c) { return r * 64 + (c ^ ((r & 7) << 3)); }

__global__ __launch_bounds__(128) void attn_tc_kernel(
    const float* __restrict__ Q, const float* __restrict__ KV, float* __restrict__ O)
{
    extern __shared__ uint32_t smemA[];
    uint32_t* Qs = smemA;
    uint32_t* Ks = smemA + 4096;
    uint32_t* Vs = smemA + 8192;
    uint32_t* Ps = smemA + 12288;

    const int tid  = threadIdx.x;
    const int lane = tid & 31;
    const int wid  = tid >> 5;
    const int gid  = lane >> 2;
    const int tid4 = lane & 3;
    const int rb   = wid * 16;
    const int bh   = blockIdx.y;
    const int b    = bh >> 4;
    const int h    = bh & 15;
    const int q0   = blockIdx.x * 64;

    // ---- Q tile (scale folded) ----
    #pragma unroll
    for (int p = 0; p < 8; p++) {
        int idx = tid + p * 128;
        int r = idx >> 4, c4 = (idx & 15) * 4;
        float4 v = *reinterpret_cast<const float4*>(
            &Q[(size_t)(b * TQ + q0 + r) * EMBED + h * HDIM + c4]);
        uint4 t = { f2tf(v.x * 0.125f), f2tf(v.y * 0.125f),
                    f2tf(v.z * 0.125f), f2tf(v.w * 0.125f) };
        *reinterpret_cast<uint4*>(&Qs[asw(r, c4)]) = t;
    }

    // ---- prefetch K tile 0 into regs ----
    float4 kreg[8];
    #pragma unroll
    for (int p = 0; p < 8; p++) {
        int idx = tid + p * 128;
        int r = idx >> 4, c4 = (idx & 15) * 4;
        kreg[p] = *reinterpret_cast<const float4*>(
            &KV[(size_t)(b * TK + r) * (2 * EMBED) + h * HDIM + c4]);
    }

    float m0 = -1e30f, m1 = -1e30f, l0 = 0.0f, l1 = 0.0f;
    float o[8][4] = {};

    for (int kt = 0; kt < TK; kt += 64) {
        // ---- commit K regs -> Ks ----
        #pragma unroll
        for (int p = 0; p < 8; p++) {
            int idx = tid + p * 128;
            int r = idx >> 4, c4 = (idx & 15) * 4;
            uint4 t = { f2tf(kreg[p].x), f2tf(kreg[p].y), f2tf(kreg[p].z), f2tf(kreg[p].w) };
            *reinterpret_cast<uint4*>(&Ks[asw(r, c4)]) = t;
        }
        __syncthreads();   // Ks (and Qs on iter 0) visible; prev-iter Ps/Vs reads done

        // ---- issue V global loads (consumed after softmax) ----
        float4 vreg[8];
        #pragma unroll
        for (int p = 0; p < 8; p++) {
            int idx = tid + p * 128;
            int r = idx >> 4, c4 = (idx & 15) * 4;
            vreg[p] = *reinterpret_cast<const float4*>(
                &KV[(size_t)(b * TK + kt + r) * (2 * EMBED) + EMBED + h * HDIM + c4]);
        }

        // ---- S = Q @ K^T ----
        float s[8][4] = {};
        #pragma unroll
        for (int ks = 0; ks < 8; ks++) {
            const int k = ks * 8;
            uint32_t a[4];
            a[0] = Qs[asw(rb + gid,     k + tid4)];
            a[1] = Qs[asw(rb + gid + 8, k + tid4)];
            a[2] = Qs[asw(rb + gid,     k + tid4 + 4)];
            a[3] = Qs[asw(rb + gid + 8, k + tid4 + 4)];
            #pragma unroll
            for (int ni = 0; ni < 8; ni++) {
                const int n = ni * 8;
                uint32_t bfr[2];
                bfr[0] = Ks[asw(n + gid, k + tid4)];
                bfr[1] = Ks[asw(n + gid, k + tid4 + 4)];
                mma_tf32(s[ni], a, bfr);
            }
        }

        // ---- online softmax (quad-lane reductions, warp-local rows) ----
        float tmax0 = -1e30f, tmax1 = -1e30f;
        #pragma unroll
        for (int ni = 0; ni < 8; ni++) {
            tmax0 = fmaxf(tmax0, fmaxf(s[ni][0], s[ni][1]));
            tmax1 = fmaxf(tmax1, fmaxf(s[ni][2], s[ni][3]));
        }
        tmax0 = fmaxf(tmax0, __shfl_xor_sync(0xffffffffu, tmax0, 1, 4));
        tmax0 = fmaxf(tmax0, __shfl_xor_sync(0xffffffffu, tmax0, 2, 4));
        tmax1 = fmaxf(tmax1, __shfl_xor_sync(0xffffffffu, tmax1, 1, 4));
        tmax1 = fmaxf(tmax1, __shfl_xor_sync(0xffffffffu, tmax1, 2, 4));

        float mn0 = fmaxf(m0, tmax0), mn1 = fmaxf(m1, tmax1);
        float al0 = __expf(m0 - mn0), al1 = __expf(m1 - mn1);
        float rs0 = 0.0f, rs1 = 0.0f;
        #pragma unroll
        for (int ni = 0; ni < 8; ni++) {
            s[ni][0] = __expf(s[ni][0] - mn0);
            s[ni][1] = __expf(s[ni][1] - mn0);
            s[ni][2] = __expf(s[ni][2] - mn1);
            s[ni][3] = __expf(s[ni][3] - mn1);
            rs0 += s[ni][0] + s[ni][1];
            rs1 += s[ni][2] + s[ni][3];
        }
        rs0 += __shfl_xor_sync(0xffffffffu, rs0, 1, 4);
        rs0 += __shfl_xor_sync(0xffffffffu, rs0, 2, 4);
        rs1 += __shfl_xor_sync(0xffffffffu, rs1, 1, 4);
        rs1 += __shfl_xor_sync(0xffffffffu, rs1, 2, 4);
        l0 = l0 * al0 + rs0;  m0 = mn0;
        l1 = l1 * al1 + rs1;  m1 = mn1;
        #pragma unroll
        for (int ni = 0; ni < 8; ni++) {
            o[ni][0] *= al0; o[ni][1] *= al0;
            o[ni][2] *= al1; o[ni][3] *= al1;
        }

        // ---- stage P and commit V regs -> Vs ----
        #pragma unroll
        for (int ni = 0; ni < 8; ni++) {
            int col = ni * 8 + 2 * tid4;
            Ps[asw(rb + gid, col)]         = f2tf(s[ni][0]);
            Ps[asw(rb + gid, col) + 1]     = f2tf(s[ni][1]);
            Ps[asw(rb + gid + 8, col)]     = f2tf(s[ni][2]);
            Ps[asw(rb + gid + 8, col) + 1] = f2tf(s[ni][3]);
        }
        #pragma unroll
        for (int p = 0; p < 8; p++) {
            int idx = tid + p * 128;
            int r = idx >> 4, c4 = (idx & 15) * 4;
            uint4 t = { f2tf(vreg[p].x), f2tf(vreg[p].y), f2tf(vreg[p].z), f2tf(vreg[p].w) };
            *reinterpret_cast<uint4*>(&Vs[asw(r, c4)]) = t;
        }
        __syncthreads();   // Ps/Vs visible; all S-reads of Ks done

        // ---- prefetch next K tile (overlaps PV mma) ----
        if (kt + 64 < TK) {
            #pragma unroll
            for (int p = 0; p < 8; p++) {
                int idx = tid + p * 128;
                int r = idx >> 4, c4 = (idx & 15) * 4;
                kreg[p] = *reinterpret_cast<const float4*>(
                    &KV[(size_t)(b * TK + kt + 64 + r) * (2 * EMBED) + h * HDIM + c4]);
            }
        }

        // ---- O += P @ V ----
        #pragma unroll
        for (int ks = 0; ks < 8; ks++) {
            const int k = ks * 8;
            uint32_t a[4];
            a[0] = Ps[asw(rb + gid,     k + tid4)];
            a[1] = Ps[asw(rb + gid + 8, k + tid4)];
            a[2] = Ps[asw(rb + gid,     k + tid4 + 4)];
            a[3] = Ps[asw(rb + gid + 8, k + tid4 + 4)];
            #pragma unroll
            for (int ni = 0; ni < 8; ni++) {
                const int n = ni * 8;
                uint32_t bfr[2];
                bfr[0] = Vs[asw(k + tid4,     n + gid)];
                bfr[1] = Vs[asw(k + tid4 + 4, n + gid)];
                mma_tf32(o[ni], a, bfr);
            }
        }
    }

    float inv0 = 1.0f / l0, inv1 = 1.0f / l1;
    #pragma unroll
    for (int ni = 0; ni < 8; ni++) {
        int col = h * HDIM + ni * 8 + 2 * tid4;
        size_t r0 = (size_t)(b * TQ + q0 + rb + gid) * EMBED;
        size_t r1 = (size_t)(b * TQ + q0 + rb + gid + 8) * EMBED;
        float2 v0 = { o[ni][0] * inv0, o[ni][1] * inv0 };
        float2 v1 = { o[ni][2] * inv1, o[ni][3] * inv1 };
        *reinterpret_cast<float2*>(&O[r0 + col]) = v0;
        *reinterpret_cast<float2*>(&O[r1 + col]) = v1;
    }
}

// ---------------------------------------------------------------------------
extern "C" void kernel_launch(void* const* d_in, const int* in_sizes, int n_in,
                              void* d_out, int out_size)
{
    const float* query   = (const float*)d_in[0];
    const float* context = (const float*)d_in[1];
    const float* Wq      = (const float*)d_in[2];
    const float* bq      = (const float*)d_in[3];
    const float* Wkv     = (const float*)d_in[4];
    const float* bkv     = (const float*)d_in[5];
    const float* Wo      = (const float*)d_in[6];
    const float* bo      = (const float*)d_in[7];
    float* out = (float*)d_out;

    float *qbuf = nullptr, *kvbuf = nullptr, *obuf = nullptr;
    cudaGetSymbolAddress((void**)&qbuf,  g_Q);
    cudaGetSymbolAddress((void**)&kvbuf, g_KV);
    cudaGetSymbolAddress((void**)&obuf,  g_O);

    static bool attr_set = false;
    if (!attr_set) {
        cudaFuncSetAttribute(attn_tc_kernel,
                             cudaFuncAttributeMaxDynamicSharedMemorySize, 65536);
        attr_set = true;
    }

    // Fused Q + KV projections (one wave train)
    qkv_proj_kernel<<<dim3(24, MROWS / 128), 256>>>(
        query, context, Wq, bq, Wkv, bkv, qbuf, kvbuf);

    // Attention core
    attn_tc_kernel<<<dim3(TQ / 64, BATCH * NHEADS), 128, 65536>>>(qbuf, kvbuf, obuf);

    // Output projection
    oproj_kernel<<<dim3(EMBED / 128, MROWS / 128), 256>>>(obuf, Wo, bo, out);
}

// round 4
// speedup vs baseline: 5.5534x; 1.2090x over previous
#include <cuda_runtime.h>
#include <math.h>
#include <stdint.h>

#define EMBED  1024
#define NHEADS 16
#define HDIM   64
#define BATCH  2
#define TQ     2048
#define TK     2048
#define MROWS  (BATCH*TQ)   // 4096

// Scratch (__device__ globals; allocation-free rule)
__device__ float g_Q  [(size_t)MROWS * EMBED];        // 16 MB (tf32, pre-scaled)
__device__ float g_KV [(size_t)MROWS * 2 * EMBED];    // 32 MB (tf32)
__device__ float g_O  [(size_t)MROWS * EMBED];        // 16 MB (tf32)
__device__ float g_rq [(size_t)MROWS * EMBED];        // rounded query
__device__ float g_rc [(size_t)MROWS * EMBED];        // rounded context
__device__ float g_rWq [(size_t)EMBED * EMBED];
__device__ float g_rWkv[(size_t)EMBED * 2 * EMBED];
__device__ float g_rWo [(size_t)EMBED * EMBED];

// ---------------------------------------------------------------------------
__device__ __forceinline__ uint32_t f2tf(float f) {
    uint32_t u;
    asm("cvt.rna.tf32.f32 %0, %1;" : "=r"(u) : "f"(f));
    return u;
}
__device__ __forceinline__ float f2tf_f(float f) { return __uint_as_float(f2tf(f)); }

__device__ __forceinline__ void mma_tf32(float* d, const uint32_t* a, const uint32_t* b) {
    asm volatile(
        "mma.sync.aligned.m16n8k8.row.col.f32.tf32.tf32.f32 "
        "{%0,%1,%2,%3}, {%4,%5,%6,%7}, {%8,%9}, {%0,%1,%2,%3};"
        : "+f"(d[0]), "+f"(d[1]), "+f"(d[2]), "+f"(d[3])
        : "r"(a[0]), "r"(a[1]), "r"(a[2]), "r"(a[3]), "r"(b[0]), "r"(b[1]));
}

__device__ __forceinline__ void cpa16(uint32_t dst, const float* src) {
    asm volatile("cp.async.cg.shared.global [%0], [%1], 16;" :: "r"(dst), "l"(src));
}
__device__ __forceinline__ void cpa_commit() { asm volatile("cp.async.commit_group;"); }
__device__ __forceinline__ void cpa_wait1()  { asm volatile("cp.async.wait_group 1;"); }
__device__ __forceinline__ void cpa_wait0()  { asm volatile("cp.async.wait_group 0;"); }

// ---------------------------------------------------------------------------
// Pre-round pass: dst = tf32_rna(src), vectorized.
// ---------------------------------------------------------------------------
__global__ void round_tf32_kernel(const float4* __restrict__ src,
                                  float4* __restrict__ dst, int n4)
{
    int i = blockIdx.x * blockDim.x + threadIdx.x;
    if (i < n4) {
        float4 v = src[i];
        float4 r = { f2tf_f(v.x), f2tf_f(v.y), f2tf_f(v.z), f2tf_f(v.w) };
        dst[i] = r;
    }
}

// ---------------------------------------------------------------------------
// Projection GEMM: 128x128 tile, BK=32, 256 thr, 3-stage cp.async ring,
// lookahead-1 (single __syncthreads per iter; overwrite target is the buffer
// of iter t-2, protected by iter t-1's barrier).
// Inputs already tf32-rounded. ROUND: round output (and scale) at store.
// ---------------------------------------------------------------------------
#define GSTG 8704            // floats per stage: A 128*36 + W 32*128
#define GASZ 4608

template <bool ROUND>
__device__ __forceinline__ void gemm_body(
    float* smem,
    const float* __restrict__ A, const float* __restrict__ W,
    const float* __restrict__ bias, float* __restrict__ C,
    int N, int K, int row0, int col0, float oscale)
{
    const int tid    = threadIdx.x;
    const int lane   = tid & 31;
    const int wid    = tid >> 5;
    const int gid    = lane >> 2;
    const int tid4   = lane & 3;
    const int warp_m = wid & 1;
    const int warp_n = wid >> 1;
    const uint32_t sbase = (uint32_t)__cvta_generic_to_shared(smem);

    auto issue_stage = [&](int stage, int k0) {
        #pragma unroll
        for (int p = 0; p < 4; p++) {
            int idx = tid + p * 256;
            int r = idx >> 3, c4 = (idx & 7) << 2;
            cpa16(sbase + (uint32_t)(stage * GSTG + r * 36 + c4) * 4,
                  &A[(size_t)(row0 + r) * K + k0 + c4]);
            int rw = idx >> 5, cw = (idx & 31) << 2;
            cpa16(sbase + (uint32_t)(stage * GSTG + GASZ + rw * 128 + (cw ^ ((rw & 3) << 3))) * 4,
                  &W[(size_t)(k0 + rw) * N + col0 + cw]);
        }
        cpa_commit();
    };

    const int T = K / 32;
    issue_stage(0, 0);

    float acc[4][4][4] = {};

    for (int t = 0; t < T; t++) {
        if (t + 1 < T) { issue_stage((t + 1) % 3, (t + 1) * 32); cpa_wait1(); }
        else           { cpa_wait0(); }
        __syncthreads();

        const uint32_t* As = (const uint32_t*)smem + (t % 3) * GSTG;
        const uint32_t* Ws = As + GASZ;

        #pragma unroll
        for (int ks = 0; ks < 4; ks++) {
            const int k = ks * 8;
            uint32_t a[4][4];
            #pragma unroll
            for (int mi = 0; mi < 4; mi++) {
                int rb = warp_m * 64 + mi * 16;
                a[mi][0] = As[(rb + gid)     * 36 + k + tid4];
                a[mi][1] = As[(rb + gid + 8) * 36 + k + tid4];
                a[mi][2] = As[(rb + gid)     * 36 + k + tid4 + 4];
                a[mi][3] = As[(rb + gid + 8) * 36 + k + tid4 + 4];
            }
            uint32_t b[4][2];
            #pragma unroll
            for (int ni = 0; ni < 4; ni++) {
                int cb = warp_n * 32 + ni * 8;
                int r1 = k + tid4, r2 = k + tid4 + 4;
                b[ni][0] = Ws[r1 * 128 + ((cb + gid) ^ ((r1 & 3) << 3))];
                b[ni][1] = Ws[r2 * 128 + ((cb + gid) ^ ((r2 & 3) << 3))];
            }
            #pragma unroll
            for (int mi = 0; mi < 4; mi++)
                #pragma unroll
                for (int ni = 0; ni < 4; ni++)
                    mma_tf32(acc[mi][ni], a[mi], b[ni]);
        }
        __syncthreads();
    }

    #pragma unroll
    for (int mi = 0; mi < 4; mi++) {
        int row = row0 + warp_m * 64 + mi * 16 + gid;
        #pragma unroll
        for (int ni = 0; ni < 4; ni++) {
            int col = col0 + warp_n * 32 + ni * 8 + 2 * tid4;
            float b0 = bias[col], b1 = bias[col + 1];
            float x0 = acc[mi][ni][0] + b0, x1 = acc[mi][ni][1] + b1;
            float x2 = acc[mi][ni][2] + b0, x3 = acc[mi][ni][3] + b1;
            if (ROUND) {
                x0 = f2tf_f(x0 * oscale); x1 = f2tf_f(x1 * oscale);
                x2 = f2tf_f(x2 * oscale); x3 = f2tf_f(x3 * oscale);
            }
            float2 v0 = { x0, x1 }, v1 = { x2, x3 };
            *reinterpret_cast<float2*>(&C[(size_t)row       * N + col]) = v0;
            *reinterpret_cast<float2*>(&C[(size_t)(row + 8) * N + col]) = v1;
        }
    }
}

// Fused Q + KV projection: grid.x 0..7 -> Q (scale 0.125), 8..23 -> KV
__global__ __launch_bounds__(256, 2) void qkv_proj_kernel(
    const float* __restrict__ query, const float* __restrict__ context,
    const float* __restrict__ Wq, const float* __restrict__ bq,
    const float* __restrict__ Wkv, const float* __restrict__ bkv,
    float* __restrict__ qbuf, float* __restrict__ kvbuf)
{
    extern __shared__ float smem[];
    const int row0 = blockIdx.y * 128;
    if (blockIdx.x < 8)
        gemm_body<true>(smem, query, Wq, bq, qbuf, EMBED, EMBED,
                        row0, blockIdx.x * 128, 0.125f);
    else
        gemm_body<true>(smem, context, Wkv, bkv, kvbuf, 2 * EMBED, EMBED,
                        row0, (blockIdx.x - 8) * 128, 1.0f);
}

__global__ __launch_bounds__(256, 2) void oproj_kernel(
    const float* __restrict__ A, const float* __restrict__ W,
    const float* __restrict__ bias, float* __restrict__ C)
{
    extern __shared__ float smem[];
    gemm_body<false>(smem, A, W, bias, C, EMBED, EMBED,
                     blockIdx.y * 128, blockIdx.x * 128, 1.0f);
}

// ---------------------------------------------------------------------------
// Flash attention: 128 thr = 4 warps, warp-local softmax, cp.async
// double-buffered K+V stages. Q/K/V buffers pre-rounded (Q pre-scaled).
// Smem: Qs 16K | Ps 16K | 2 x (Ks 16K + Vs 16K) = 96KB -> 2 CTA/SM.
// ---------------------------------------------------------------------------
__device__ __forceinline__ int asw(int r, int c) { return r * 64 + (c ^ ((r & 7) << 3)); }

#define AQ_OFF 0
#define AP_OFF 4096
#define AKV_OFF 8192          // stage s: K at AKV_OFF + s*8192, V at +4096

__global__ __launch_bounds__(128, 2) void attn_tc_kernel(
    const float* __restrict__ Q, const float* __restrict__ KV, float* __restrict__ O)
{
    extern __shared__ float smem[];
    const uint32_t sbase = (uint32_t)__cvta_generic_to_shared(smem);

    const int tid  = threadIdx.x;
    const int lane = tid & 31;
    const int wid  = tid >> 5;
    const int gid  = lane >> 2;
    const int tid4 = lane & 3;
    const int rb   = wid * 16;
    const int bh   = blockIdx.y;
    const int b    = bh >> 4;
    const int h    = bh & 15;
    const int q0   = blockIdx.x * 64;

    auto issue_kv = [&](int stage, int kt) {
        #pragma unroll
        for (int p = 0; p < 8; p++) {
            int idx = tid + p * 128;
            int r = idx >> 4, c4 = (idx & 15) << 2;
            size_t rowb = (size_t)(b * TK + kt + r) * (2 * EMBED) + h * HDIM + c4;
            uint32_t d = sbase + (uint32_t)(AKV_OFF + stage * 8192 + asw(r, c4)) * 4;
            cpa16(d, &KV[rowb]);
            cpa16(d + 4096 * 4, &KV[rowb + EMBED]);
        }
        cpa_commit();
    };

    // prologue: group A = Q + KV tile 0; group B = KV tile 1
    #pragma unroll
    for (int p = 0; p < 8; p++) {
        int idx = tid + p * 128;
        int r = idx >> 4, c4 = (idx & 15) << 2;
        cpa16(sbase + (uint32_t)(AQ_OFF + asw(r, c4)) * 4,
              &Q[(size_t)(b * TQ + q0 + r) * EMBED + h * HDIM + c4]);
    }
    {
        #pragma unroll
        for (int p = 0; p < 8; p++) {
            int idx = tid + p * 128;
            int r = idx >> 4, c4 = (idx & 15) << 2;
            size_t rowb = (size_t)(b * TK + r) * (2 * EMBED) + h * HDIM + c4;
            uint32_t d = sbase + (uint32_t)(AKV_OFF + asw(r, c4)) * 4;
            cpa16(d, &KV[rowb]);
            cpa16(d + 4096 * 4, &KV[rowb + EMBED]);
        }
        cpa_commit();
    }
    issue_kv(1, 64);

    const uint32_t* Qs = (const uint32_t*)smem + AQ_OFF;
    uint32_t*       Ps = (uint32_t*)smem + AP_OFF;

    float m0 = -1e30f, m1 = -1e30f, l0 = 0.0f, l1 = 0.0f;
    float o[8][4] = {};
    const int NT = TK / 64;   // 32

    for (int t = 0; t < NT; t++) {
        if (t < NT - 1) cpa_wait1(); else cpa_wait0();
        __syncthreads();                      // stage t visible to all warps

        const uint32_t* Ks = (const uint32_t*)smem + AKV_OFF + (t & 1) * 8192;
        const uint32_t* Vs = Ks + 4096;

        // ---- S = Q @ K^T ----
        float s[8][4] = {};
        #pragma unroll
        for (int ks = 0; ks < 8; ks++) {
            const int k = ks * 8;
            uint32_t a[4];
            a[0] = Qs[asw(rb + gid,     k + tid4)];
            a[1] = Qs[asw(rb + gid + 8, k + tid4)];
            a[2] = Qs[asw(rb + gid,     k + tid4 + 4)];
            a[3] = Qs[asw(rb + gid + 8, k + tid4 + 4)];
            #pragma unroll
            for (int ni = 0; ni < 8; ni++) {
                const int n = ni * 8;
                uint32_t bfr[2];
                bfr[0] = Ks[asw(n + gid, k + tid4)];
                bfr[1] = Ks[asw(n + gid, k + tid4 + 4)];
                mma_tf32(s[ni], a, bfr);
            }
        }

        // ---- online softmax ----
        float tmax0 = -1e30f, tmax1 = -1e30f;
        #pragma unroll
        for (int ni = 0; ni < 8; ni++) {
            tmax0 = fmaxf(tmax0, fmaxf(s[ni][0], s[ni][1]));
            tmax1 = fmaxf(tmax1, fmaxf(s[ni][2], s[ni][3]));
        }
        tmax0 = fmaxf(tmax0, __shfl_xor_sync(0xffffffffu, tmax0, 1, 4));
        tmax0 = fmaxf(tmax0, __shfl_xor_sync(0xffffffffu, tmax0, 2, 4));
        tmax1 = fmaxf(tmax1, __shfl_xor_sync(0xffffffffu, tmax1, 1, 4));
        tmax1 = fmaxf(tmax1, __shfl_xor_sync(0xffffffffu, tmax1, 2, 4));

        float mn0 = fmaxf(m0, tmax0), mn1 = fmaxf(m1, tmax1);
        float al0 = __expf(m0 - mn0), al1 = __expf(m1 - mn1);
        float rs0 = 0.0f, rs1 = 0.0f;
        #pragma unroll
        for (int ni = 0; ni < 8; ni++) {
            s[ni][0] = __expf(s[ni][0] - mn0);
            s[ni][1] = __expf(s[ni][1] - mn0);
            s[ni][2] = __expf(s[ni][2] - mn1);
            s[ni][3] = __expf(s[ni][3] - mn1);
            rs0 += s[ni][0] + s[ni][1];
            rs1 += s[ni][2] + s[ni][3];
        }
        rs0 += __shfl_xor_sync(0xffffffffu, rs0, 1, 4);
        rs0 += __shfl_xor_sync(0xffffffffu, rs0, 2, 4);
        rs1 += __shfl_xor_sync(0xffffffffu, rs1, 1, 4);
        rs1 += __shfl_xor_sync(0xffffffffu, rs1, 2, 4);
        l0 = l0 * al0 + rs0;  m0 = mn0;
        l1 = l1 * al1 + rs1;  m1 = mn1;
        #pragma unroll
        for (int ni = 0; ni < 8; ni++) {
            o[ni][0] *= al0; o[ni][1] *= al0;
            o[ni][2] *= al1; o[ni][3] *= al1;
        }

        // ---- stage P (warp-private rows -> only __syncwarp needed) ----
        #pragma unroll
        for (int ni = 0; ni < 8; ni++) {
            int col = ni * 8 + 2 * tid4;
            Ps[asw(rb + gid, col)]         = f2tf(s[ni][0]);
            Ps[asw(rb + gid, col) + 1]     = f2tf(s[ni][1]);
            Ps[asw(rb + gid + 8, col)]     = f2tf(s[ni][2]);
            Ps[asw(rb + gid + 8, col) + 1] = f2tf(s[ni][3]);
        }
        __syncwarp();

        // ---- O += P @ V ----
        #pragma unroll
        for (int ks = 0; ks < 8; ks++) {
            const int k = ks * 8;
            uint32_t a[4];
            a[0] = Ps[asw(rb + gid,     k + tid4)];
            a[1] = Ps[asw(rb + gid + 8, k + tid4)];
            a[2] = Ps[asw(rb + gid,     k + tid4 + 4)];
            a[3] = Ps[asw(rb + gid + 8, k + tid4 + 4)];
            #pragma unroll
            for (int ni = 0; ni < 8; ni++) {
                const int n = ni * 8;
                uint32_t bfr[2];
                bfr[0] = Vs[asw(k + tid4,     n + gid)];
                bfr[1] = Vs[asw(k + tid4 + 4, n + gid)];
                mma_tf32(o[ni], a, bfr);
            }
        }

        __syncthreads();                      // all reads of stage t%2 done
        if (t + 2 < NT) issue_kv(t & 1, (t + 2) * 64);
    }

    // ---- write O (normalize, round to tf32 for the O-proj) ----
    float inv0 = 1.0f / l0, inv1 = 1.0f / l1;
    #pragma unroll
    for (int ni = 0; ni < 8; ni++) {
        int col = h * HDIM + ni * 8 + 2 * tid4;
        size_t r0 = (size_t)(b * TQ + q0 + rb + gid) * EMBED;
        size_t r1 = (size_t)(b * TQ + q0 + rb + gid + 8) * EMBED;
        float2 v0 = { f2tf_f(o[ni][0] * inv0), f2tf_f(o[ni][1] * inv0) };
        float2 v1 = { f2tf_f(o[ni][2] * inv1), f2tf_f(o[ni][3] * inv1) };
        *reinterpret_cast<float2*>(&O[r0 + col]) = v0;
        *reinterpret_cast<float2*>(&O[r1 + col]) = v1;
    }
}

// ---------------------------------------------------------------------------
extern "C" void kernel_launch(void* const* d_in, const int* in_sizes, int n_in,
                              void* d_out, int out_size)
{
    const float* query   = (const float*)d_in[0];
    const float* context = (const float*)d_in[1];
    const float* Wq      = (const float*)d_in[2];
    const float* bq      = (const float*)d_in[3];
    const float* Wkv     = (const float*)d_in[4];
    const float* bkv     = (const float*)d_in[5];
    const float* Wo      = (const float*)d_in[6];
    const float* bo      = (const float*)d_in[7];
    float* out = (float*)d_out;

    float *qbuf, *kvbuf, *obuf, *rq, *rc, *rWq, *rWkv, *rWo;
    cudaGetSymbolAddress((void**)&qbuf,  g_Q);
    cudaGetSymbolAddress((void**)&kvbuf, g_KV);
    cudaGetSymbolAddress((void**)&obuf,  g_O);
    cudaGetSymbolAddress((void**)&rq,    g_rq);
    cudaGetSymbolAddress((void**)&rc,    g_rc);
    cudaGetSymbolAddress((void**)&rWq,   g_rWq);
    cudaGetSymbolAddress((void**)&rWkv,  g_rWkv);
    cudaGetSymbolAddress((void**)&rWo,   g_rWo);

    static bool attr_set = false;
    if (!attr_set) {
        cudaFuncSetAttribute(qkv_proj_kernel,
                             cudaFuncAttributeMaxDynamicSharedMemorySize, 3 * GSTG * 4);
        cudaFuncSetAttribute(oproj_kernel,
                             cudaFuncAttributeMaxDynamicSharedMemorySize, 3 * GSTG * 4);
        cudaFuncSetAttribute(attn_tc_kernel,
                             cudaFuncAttributeMaxDynamicSharedMemorySize, 98304);
        attr_set = true;
    }

    // ---- pre-round inputs/weights to tf32 (rna) ----
    auto rnd = [&](const float* s, float* d, size_t n) {
        int n4 = (int)(n / 4);
        round_tf32_kernel<<<(n4 + 255) / 256, 256>>>(
            (const float4*)s, (float4*)d, n4);
    };
    rnd(query,   rq,   (size_t)MROWS * EMBED);
    rnd(context, rc,   (size_t)MROWS * EMBED);
    rnd(Wq,      rWq,  (size_t)EMBED * EMBED);
    rnd(Wkv,     rWkv, (size_t)EMBED * 2 * EMBED);
    rnd(Wo,      rWo,  (size_t)EMBED * EMBED);

    // ---- fused Q + KV projections ----
    qkv_proj_kernel<<<dim3(24, MROWS / 128), 256, 3 * GSTG * 4>>>(
        rq, rc, rWq, bq, rWkv, bkv, qbuf, kvbuf);

    // ---- attention core ----
    attn_tc_kernel<<<dim3(TQ / 64, BATCH * NHEADS), 128, 98304>>>(qbuf, kvbuf, obuf);

    // ---- output projection ----
    oproj_kernel<<<dim3(EMBED / 128, MROWS / 128), 256, 3 * GSTG * 4>>>(
        obuf, rWo, bo, out);
}